// round 1
// baseline (speedup 1.0000x reference)
#include <cuda_runtime.h>

#define N_NODES 100000
#define N_EDGES 3200000
#define D 256          // D_IN == D_OUT == 256

// Scratch: per-node degree (1 + out-edge count). __device__ global per harness rules.
__device__ float g_deg[N_NODES];

// edge_index[0] (the src row) is sorted ascending by construction in the
// reference (np.unique on src*n+dst). deg[i] = 1 + (#src == i) via two
// lower_bounds on the sorted src array. ~22 steps each, L2-resident.
__global__ void deg_kernel(const int* __restrict__ src) {
    int i = blockIdx.x * blockDim.x + threadIdx.x;
    if (i >= N_NODES) return;

    // lower_bound(src, i)
    int lo = 0, hi = N_EDGES;
    while (lo < hi) {
        int mid = (lo + hi) >> 1;
        if (src[mid] < i) lo = mid + 1; else hi = mid;
    }
    int a = lo;

    // lower_bound(src, i+1), starting from a (positions >= a all have src >= i)
    hi = N_EDGES;
    int v = i + 1;
    while (lo < hi) {
        int mid = (lo + hi) >> 1;
        if (src[mid] < v) lo = mid + 1; else hi = mid;
    }
    g_deg[i] = 1.0f + (float)(lo - a);
}

// Fused SGEMM + GraphConv epilogue:
//   out[m][n] = deg[m] * sum_k X[m][k] * W[n][k] + b[n]
// BM=128, BN=128, BK=16, 256 threads, 8x8 per-thread microtile.
__global__ __launch_bounds__(256)
void gemm_kernel(const float* __restrict__ X,
                 const float* __restrict__ W,
                 const float* __restrict__ bias,
                 float* __restrict__ out) {
    __shared__ float As[16][128];   // [k][m]
    __shared__ float Bs[16][128];   // [k][n]

    const int m0 = blockIdx.x * 128;
    const int n0 = blockIdx.y * 128;
    const int tid = threadIdx.x;
    const int ty = tid >> 4;        // 0..15 -> row group (8 rows)
    const int tx = tid & 15;        // 0..15 -> col group (8 cols)

    float acc[8][8];
    #pragma unroll
    for (int i = 0; i < 8; i++)
        #pragma unroll
        for (int j = 0; j < 8; j++)
            acc[i][j] = 0.0f;

    for (int k0 = 0; k0 < D; k0 += 16) {
        // Cooperative load: 128x16 tile = 512 float4; each thread does 2 for A, 2 for B.
        #pragma unroll
        for (int l = 0; l < 2; l++) {
            int f   = tid + l * 256;   // 0..511
            int row = f >> 2;          // 0..127
            int kq  = f & 3;           // which float4 within the 16 k's

            // A (X) tile, with row guard for the ragged last block
            int gr = m0 + row;
            float4 va = make_float4(0.f, 0.f, 0.f, 0.f);
            if (gr < N_NODES)
                va = *reinterpret_cast<const float4*>(X + (size_t)gr * D + k0 + kq * 4);
            As[kq * 4 + 0][row] = va.x;
            As[kq * 4 + 1][row] = va.y;
            As[kq * 4 + 2][row] = va.z;
            As[kq * 4 + 3][row] = va.w;

            // B (W) tile: N=256 divides evenly, no guard
            int gw = n0 + row;
            float4 vb = *reinterpret_cast<const float4*>(W + (size_t)gw * D + k0 + kq * 4);
            Bs[kq * 4 + 0][row] = vb.x;
            Bs[kq * 4 + 1][row] = vb.y;
            Bs[kq * 4 + 2][row] = vb.z;
            Bs[kq * 4 + 3][row] = vb.w;
        }
        __syncthreads();

        #pragma unroll
        for (int kk = 0; kk < 16; kk++) {
            float a[8], b[8];
            const float4* Ap = reinterpret_cast<const float4*>(&As[kk][ty * 8]);
            const float4* Bp = reinterpret_cast<const float4*>(&Bs[kk][tx * 8]);
            float4 a0 = Ap[0], a1 = Ap[1];
            float4 b0 = Bp[0], b1 = Bp[1];
            a[0]=a0.x; a[1]=a0.y; a[2]=a0.z; a[3]=a0.w;
            a[4]=a1.x; a[5]=a1.y; a[6]=a1.z; a[7]=a1.w;
            b[0]=b0.x; b[1]=b0.y; b[2]=b0.z; b[3]=b0.w;
            b[4]=b1.x; b[5]=b1.y; b[6]=b1.z; b[7]=b1.w;

            #pragma unroll
            for (int i = 0; i < 8; i++)
                #pragma unroll
                for (int j = 0; j < 8; j++)
                    acc[i][j] = fmaf(a[i], b[j], acc[i][j]);
        }
        __syncthreads();
    }

    // Epilogue: out[m][n] = deg[m] * acc + b[n]
    float bj[8];
    #pragma unroll
    for (int j = 0; j < 8; j++) bj[j] = bias[n0 + tx * 8 + j];

    #pragma unroll
    for (int i = 0; i < 8; i++) {
        int row = m0 + ty * 8 + i;
        if (row < N_NODES) {
            float d = g_deg[row];
            float4 o0, o1;
            o0.x = fmaf(d, acc[i][0], bj[0]);
            o0.y = fmaf(d, acc[i][1], bj[1]);
            o0.z = fmaf(d, acc[i][2], bj[2]);
            o0.w = fmaf(d, acc[i][3], bj[3]);
            o1.x = fmaf(d, acc[i][4], bj[4]);
            o1.y = fmaf(d, acc[i][5], bj[5]);
            o1.z = fmaf(d, acc[i][6], bj[6]);
            o1.w = fmaf(d, acc[i][7], bj[7]);
            float* op = out + (size_t)row * D + n0 + tx * 8;
            *reinterpret_cast<float4*>(op)     = o0;
            *reinterpret_cast<float4*>(op + 4) = o1;
        }
    }
}

extern "C" void kernel_launch(void* const* d_in, const int* in_sizes, int n_in,
                              void* d_out, int out_size) {
    const float* x  = (const float*)d_in[0];   // [100000, 256] f32
    const int*   ei = (const int*)d_in[1];     // [2, 3200000] i32, row 0 = src (sorted)
    const float* W  = (const float*)d_in[2];   // [256, 256] f32
    const float* b  = (const float*)d_in[3];   // [256] f32
    float* out = (float*)d_out;                // [100000, 256] f32

    deg_kernel<<<(N_NODES + 255) / 256, 256>>>(ei);  // src row = ei[0 .. N_EDGES)

    dim3 grid((N_NODES + 127) / 128, D / 128);
    gemm_kernel<<<grid, 256>>>(x, W, b, out);
}